// round 16
// baseline (speedup 1.0000x reference)
#include <cuda_runtime.h>
#include <cuda_fp16.h>
#include <math.h>
#include <stdint.h>

// ---------------------------------------------------------------------------
// Problem constants
// ---------------------------------------------------------------------------
#define B_SZ    64
#define L_SZ    512
#define D_EMB   768
#define D_HID   17
#define D_OBS   17
#define N_SRC   24
#define NM1     16
#define TRANS_COLS (D_HID * D_HID)   // 289
#define M_ROWS  (B_SZ * L_SZ)        // 32768
#define N_PAD   320                  // padded B rows (289..319 zero)

// output layout (flattened concat of the 5 reference outputs, in order)
#define OFF_TRANS 0ULL
#define SZ_TRANS  ((size_t)M_ROWS * TRANS_COLS)
#define OFF_EMISS (OFF_TRANS + SZ_TRANS)
#define SZ_EMISS  ((size_t)B_SZ * N_SRC * TRANS_COLS)
#define OFF_O2O   (OFF_EMISS + SZ_EMISS)
#define SZ_O2O    ((size_t)B_SZ * N_SRC)
#define OFF_L2L   (OFF_O2O + SZ_O2O)
#define SZ_L2L    ((size_t)B_SZ * N_SRC * NM1)
#define OFF_WXOR  (OFF_L2L + SZ_L2L)
#define SZ_WXOR   ((size_t)B_SZ * N_SRC * NM1 * NM1)

// scratch (device globals; no allocations allowed)
__device__ __align__(16) __half g_Wh[N_PAD * D_EMB];

// ---------------------------------------------------------------------------
// Helpers (plain sm_100-compatible: mma.sync / ldmatrix / cp.async only)
// ---------------------------------------------------------------------------
__device__ __forceinline__ uint32_t smem_to_u32(const void* p) {
    uint32_t a;
    asm("{ .reg .u64 t; cvta.to.shared.u64 t, %1; cvt.u32.u64 %0, t; }" : "=r"(a) : "l"(p));
    return a;
}
__device__ __forceinline__ void mma16816(float* d, const uint32_t* a, uint32_t b0, uint32_t b1) {
    asm volatile("mma.sync.aligned.m16n8k16.row.col.f32.f16.f16.f32 "
        "{%0,%1,%2,%3},{%4,%5,%6,%7},{%8,%9},{%0,%1,%2,%3};"
        : "+f"(d[0]), "+f"(d[1]), "+f"(d[2]), "+f"(d[3])
        : "r"(a[0]), "r"(a[1]), "r"(a[2]), "r"(a[3]), "r"(b0), "r"(b1));
}
__device__ __forceinline__ void ldsm4(uint32_t* r, uint32_t addr) {
    asm volatile("ldmatrix.sync.aligned.m8n8.x4.shared.b16 {%0,%1,%2,%3}, [%4];"
        : "=r"(r[0]), "=r"(r[1]), "=r"(r[2]), "=r"(r[3]) : "r"(addr));
}
#define CP_ASYNC16(dst, src) \
    asm volatile("cp.async.cg.shared.global [%0], [%1], 16;" :: "r"(dst), "l"(src) : "memory")
#define CP_COMMIT() asm volatile("cp.async.commit_group;" ::: "memory")
#define CP_WAIT(n)  asm volatile("cp.async.wait_group %0;" :: "n"(n) : "memory")

// fp16 hi/lo split of two fp32 values, packed as half2 words
__device__ __forceinline__ void split2h(float x, float y, uint32_t& h, uint32_t& l) {
    __half hx = __float2half_rn(x), hy = __float2half_rn(y);
    float rx = x - __half2float(hx), ry = y - __half2float(hy);
    __half lx = __float2half_rn(rx), ly = __float2half_rn(ry);
    h = ((uint32_t)__half_as_ushort(hy) << 16) | __half_as_ushort(hx);
    l = ((uint32_t)__half_as_ushort(ly) << 16) | __half_as_ushort(lx);
}
__device__ __forceinline__ float sigmoidf_(float x) { return 1.f / (1.f + __expf(-x)); }

// ---------------------------------------------------------------------------
// Kernel 0: convert W_trans to fp16, zero-pad rows 289..319
// ---------------------------------------------------------------------------
__global__ __launch_bounds__(256) void convert_W_kernel(const float* __restrict__ W)
{
    int idx = blockIdx.x * 256 + threadIdx.x;          // < 320*768
    int row = idx / D_EMB;
    float v = (row < TRANS_COLS) ? W[idx] : 0.f;
    g_Wh[idx] = __float2half_rn(v);
}

// ---------------------------------------------------------------------------
// Fused kernel (256 threads, 2 CTAs/SM): blocks 0..511 = GEMM tiles
// (64 rows x 320 cols, 2Mx4N warps, fp16 2-term split, 3-stage pipeline,
// one barrier/iter, fused bias+softmax); blocks 512..575 = small path.
// ---------------------------------------------------------------------------
#define BK        32
#define NK_ITERS  (D_EMB / BK)            // 24
#define PITCH     80                      // bytes per 32-fp16 row
#define NSTAGE    3
#define BM        64
#define A_BUF_SZ  (BM * PITCH)            // 5120
#define B_BUF_SZ  (N_PAD * PITCH)         // 25600
#define SM_A      0                       // 3 stages x 2 (hi/lo) x 5120 = 30720
#define SM_B      30720                   // 3 stages x 25600 = 76800 -> 107520
#define STAG_PITCH 305                    // staging 64x305x4 = 78080 (< 107520)
#define SM_BIAS   107520                  // 289 floats
#define SM_TOTAL  108800

#define A_OFF(st,hl) (SM_A + ((st)*2 + (hl)) * A_BUF_SZ)
#define B_OFF(st)    (SM_B + (st) * B_BUF_SZ)

#define N_GEMM_BLOCKS 512
#define GRID_TOTAL    (N_GEMM_BLOCKS + B_SZ)
#define NTHR          256

__global__ __launch_bounds__(NTHR, 2) void fused_kernel(
    const float* __restrict__ embs,
    const float* __restrict__ bias,
    const float* __restrict__ W2o, const float* __restrict__ b2o,
    const float* __restrict__ W2e, const float* __restrict__ b2e,
    const float* __restrict__ Wexp, const float* __restrict__ bexp,
    const float* __restrict__ lut,
    float* __restrict__ out)
{
    extern __shared__ char smem[];
    const int bid = blockIdx.x;
    const int tid = threadIdx.x;

    if (bid >= N_GEMM_BLOCKS) {
        // =============== SMALL PATH: one block per batch row b ==============
        const int b = bid - N_GEMM_BLOCKS;
        float* x0   = (float*)smem;              // 768
        float* so2o = x0 + D_EMB;                // 24
        float* l2l  = so2o + N_SRC;              // 384
        float* wsc  = l2l + N_SRC * NM1;         // 384
        const int wid = tid >> 5, lane = tid & 31;

        const float* xrow = embs + (size_t)b * L_SZ * D_EMB;
        for (int i = tid; i < D_EMB; i += NTHR) x0[i] = xrow[i];
        __syncthreads();

        // 792 dot products, warp per column (8 warps)
        for (int col = wid; col < 24 + 2 * N_SRC * NM1; col += 8) {
            const float* w; float bv; float* dst; int isExp = 0;
            if (col < 24) {
                w = W2o + (size_t)col * D_EMB;  bv = b2o[col];  dst = &so2o[col];
            } else if (col < 24 + N_SRC * NM1) {
                int c = col - 24;
                w = W2e + (size_t)c * D_EMB;    bv = b2e[c];    dst = &l2l[c];
            } else {
                int c = col - 24 - N_SRC * NM1;
                w = Wexp + (size_t)c * D_EMB;   bv = bexp[c];   dst = &wsc[c]; isExp = 1;
            }
            float s = 0.f;
            for (int k = lane; k < D_EMB; k += 32) s = fmaf(x0[k], w[k], s);
#pragma unroll
            for (int o = 16; o > 0; o >>= 1) s += __shfl_xor_sync(0xffffffffu, s, o);
            if (lane == 0) {
                s += bv;
                *dst = isExp ? sigmoidf_(s) : s;
            }
        }
        __syncthreads();
        if (tid < N_SRC) so2o[tid] = sigmoidf_(so2o[tid]);
        __syncthreads();

        // softmax over 24 sources per column j + prob_scaling (8 warps, 2 cols each)
        for (int j = wid; j < NM1; j += 8) {
            float x = (lane < N_SRC) ? l2l[lane * NM1 + j] : -1e30f;
            float mx = x;
#pragma unroll
            for (int o = 16; o > 0; o >>= 1) mx = fmaxf(mx, __shfl_xor_sync(0xffffffffu, mx, o));
            float e = (lane < N_SRC) ? __expf(x - mx) : 0.f;
            float s = e;
#pragma unroll
            for (int o = 16; o > 0; o >>= 1) s += __shfl_xor_sync(0xffffffffu, s, o);
            if (lane < N_SRC) {
                const float xn = e / s;
                const float r = 1.f / 24.f;
                const float omr = 1.f - r;
                const float bco = 1.f / (omr * omr * omr);
                float om = 1.f - xn;
                float om2 = om * om;
                l2l[lane * NM1 + j] = (xn < r) ? xn : (1.f - bco * om2 * om2);
            }
        }
        __syncthreads();

        if (tid < N_SRC) out[OFF_O2O + (size_t)b * N_SRC + tid] = so2o[tid];
        for (int t = tid; t < N_SRC * NM1; t += NTHR)
            out[OFF_L2L + (size_t)b * N_SRC * NM1 + t] = l2l[t];

        // scaled_wxor[b,s,i,j] = wsc[s,j] * lut[s,j,i]
        for (int t = tid; t < N_SRC * NM1; t += NTHR) {
            const int s = t >> 4;
            const int i = t & 15;
            float* dst = out + OFF_WXOR + (size_t)b * (N_SRC * NM1 * NM1) + (size_t)t * NM1;
#pragma unroll
            for (int j = 0; j < NM1; j++)
                dst[j] = wsc[s * NM1 + j] * lut[s * 256 + j * NM1 + i];
        }

        // emission probs: 24 sources x 17 rows (408 items)
        const float tp = 1.f / (float)D_OBS;
        for (int t = tid; t < N_SRC * D_HID; t += NTHR) {
            const int s   = t / D_HID;
            const int row = t - s * D_HID;
            float vals[D_HID];
            if (row == 0) {
                const float o = so2o[s];
                vals[0] = o;
                const float rest = (1.f - o) * (1.f / (float)NM1);
#pragma unroll
                for (int j = 1; j < D_HID; j++) vals[j] = rest;
            } else {
                const int i = row - 1;
                const float x = l2l[s * NM1 + i];
                const float wf = (x < tp) ? ((float)D_OBS * x * x) : x;
                const float omx = 1.f - x;
                vals[0] = omx * (1.f - wf);
                const float nd = omx * wf * (1.f / 15.f);
#pragma unroll
                for (int j = 0; j < NM1; j++) {
                    float base = (i == j) ? x : nd;
                    vals[j + 1] = base + wsc[s * NM1 + j] * lut[s * 256 + j * NM1 + i];
                }
            }
            float ssum = 0.f;
#pragma unroll
            for (int q = 0; q < D_HID; q++) {
                float rv = fmaf(vals[q], 99.f, 1.f);
                vals[q] = rv;
                ssum += rv;
            }
            const float inv = 1.f / ssum;
            float* dst = out + OFF_EMISS + (size_t)b * N_SRC * TRANS_COLS
                             + (size_t)s * TRANS_COLS + (size_t)row * D_HID;
#pragma unroll
            for (int q = 0; q < D_HID; q++) dst[q] = vals[q] * inv;
        }
        return;
    }

    // ====================== GEMM PATH ======================================
    const uint32_t smem_u = smem_to_u32(smem);
    const int wid  = tid >> 5;
    const int lane = tid & 31;
    const int mw   = wid >> 2;           // 0..1  (M warp: 32 rows, 2 m16 frags)
    const int nw   = wid & 3;            // 0..3  (N warp: 80 cols, 10 n8 tiles)
    const int m0   = bid * BM;

    // bias to smem
    for (int i = tid; i < TRANS_COLS; i += NTHR)
        *(float*)(smem + SM_BIAS + i * 4) = bias[i];

    // per-lane ldmatrix offsets
    const uint32_t aLaneOff = (uint32_t)((mw * 32 + (lane & 15)) * PITCH + (lane >> 4) * 16);
    const uint32_t rowInPair = (lane & 7) + ((lane & 16) >> 1);       // 0..15
    const uint32_t khalf = (lane >> 3) & 1;
    const uint32_t bLaneOff = (uint32_t)((nw * 80 + rowInPair) * PITCH + khalf * 16);

    // A global-load mapping: each thread loads 8 fp32 (2 float4) per chunk
    const int arow = tid >> 2;           // 0..63
    const int aq   = tid & 3;
    const float* aSrcBase = embs + (size_t)(m0 + arow) * D_EMB + aq * 8;

    float acc[20][4];                    // [m*10 + j][quad]
#pragma unroll
    for (int j = 0; j < 20; j++)
#pragma unroll
        for (int q = 0; q < 4; q++) acc[j][q] = 0.f;

    // ---- prologue: A regs chunk 0, B chunk 0 -> stage 0
    float4 aU = ((const float4*)(aSrcBase))[0];
    float4 aV = ((const float4*)(aSrcBase))[1];
    for (int c = tid; c < 1280; c += NTHR) {     // 320 rows x 4 segs
        const int r = c >> 2;
        const int seg = c & 3;
        const __half* src = g_Wh + (size_t)r * D_EMB + seg * 8;
        CP_ASYNC16(smem_u + B_OFF(0) + r * PITCH + seg * 16, src);
    }
    CP_COMMIT();

    for (int it = 0; it < NK_ITERS; it++) {
        const int st = it % NSTAGE;
        // prefetch B chunk it+1 into stage (it+1)%3.
        if (it < NK_ITERS - 1) {
            const int k0 = (it + 1) * BK;
            const int stn = (it + 1) % NSTAGE;
            for (int c = tid; c < 1280; c += NTHR) {
                const int r = c >> 2;
                const int seg = c & 3;
                const __half* src = g_Wh + (size_t)r * D_EMB + k0 + seg * 8;
                CP_ASYNC16(smem_u + B_OFF(stn) + r * PITCH + seg * 16, src);
            }
            CP_COMMIT();
        }
        // convert A chunk it -> stage st (laggards read stage (it-1)%3)
        {
            uint32_t hi[4], lo[4];
            split2h(aU.x, aU.y, hi[0], lo[0]);
            split2h(aU.z, aU.w, hi[1], lo[1]);
            split2h(aV.x, aV.y, hi[2], lo[2]);
            split2h(aV.z, aV.w, hi[3], lo[3]);
            const uint32_t d = arow * PITCH + aq * 16;
            *(uint4*)(smem + A_OFF(st, 0) + d) = make_uint4(hi[0], hi[1], hi[2], hi[3]);
            *(uint4*)(smem + A_OFF(st, 1) + d) = make_uint4(lo[0], lo[1], lo[2], lo[3]);
        }
        if (it < NK_ITERS - 1) {
            const float* s = aSrcBase + (it + 1) * BK;
            aU = ((const float4*)s)[0];
            aV = ((const float4*)s)[1];
        }
        if (it < NK_ITERS - 1) { CP_WAIT(1); } else { CP_WAIT(0); }
        __syncthreads();   // single barrier per iteration

        // ---- compute on stage st (2 terms: Ah*Bh + Al*Bh)
        const uint32_t aHi = smem_u + A_OFF(st, 0) + aLaneOff;
        const uint32_t aLo = smem_u + A_OFF(st, 1) + aLaneOff;
        const uint32_t bHi = smem_u + B_OFF(st) + bLaneOff;
#pragma unroll
        for (int s = 0; s < 2; s++) {
            const uint32_t so = s * 32;
            uint32_t ah0[4], ah1[4], al0[4], al1[4];
            ldsm4(ah0, aHi + so);
            ldsm4(ah1, aHi + 16 * PITCH + so);
            ldsm4(al0, aLo + so);
            ldsm4(al1, aLo + 16 * PITCH + so);
#pragma unroll
            for (int jp = 0; jp < 5; jp++) {
                const uint32_t off = jp * (16 * PITCH);
                uint32_t bh[4];
                ldsm4(bh, bHi + off + so);
                mma16816(acc[2*jp],      ah0, bh[0], bh[1]);
                mma16816(acc[2*jp+1],    ah0, bh[2], bh[3]);
                mma16816(acc[10+2*jp],   ah1, bh[0], bh[1]);
                mma16816(acc[10+2*jp+1], ah1, bh[2], bh[3]);

                mma16816(acc[2*jp],      al0, bh[0], bh[1]);
                mma16816(acc[2*jp+1],    al0, bh[2], bh[3]);
                mma16816(acc[10+2*jp],   al1, bh[0], bh[1]);
                mma16816(acc[10+2*jp+1], al1, bh[2], bh[3]);
            }
        }
        // no trailing barrier (3-stage rotation guarantees safety)
    }
    __syncthreads();   // all compute done before smem is repurposed

    // ---- epilogue: accumulators -> staging smem
    float* stag = (float*)smem;
    {
        const int r0 = mw * 32 + (lane >> 2);
        const int nbase = nw * 80 + (lane & 3) * 2;
#pragma unroll
        for (int m = 0; m < 2; m++) {
            const int rA = r0 + m * 16;
#pragma unroll
            for (int j = 0; j < 10; j++) {
                const int n = nbase + j * 8;
                const float* a = acc[m * 10 + j];
                if (n < 288) {
                    stag[rA * STAG_PITCH + n]           = a[0];
                    stag[rA * STAG_PITCH + n + 1]       = a[1];
                    stag[(rA + 8) * STAG_PITCH + n]     = a[2];
                    stag[(rA + 8) * STAG_PITCH + n + 1] = a[3];
                } else if (n == 288) {
                    stag[rA * STAG_PITCH + 288]       = a[0];
                    stag[(rA + 8) * STAG_PITCH + 288] = a[2];
                }
            }
        }
    }
    __syncthreads();

    // ---- bias + softmax over contiguous 17-groups
    const float* biasS = (const float*)(smem + SM_BIAS);
    for (int t = tid; t < BM * D_HID; t += NTHR) {
        const int row = t / D_HID;
        const int g = t - row * D_HID;
        float* p = stag + row * STAG_PITCH + g * D_HID;
        const float* bb = biasS + g * D_HID;
        float v[D_HID];
        float mx = -1e30f;
#pragma unroll
        for (int j = 0; j < D_HID; j++) { v[j] = p[j] + bb[j]; mx = fmaxf(mx, v[j]); }
        float s = 0.f;
#pragma unroll
        for (int j = 0; j < D_HID; j++) { float e = __expf(v[j] - mx); v[j] = e; s += e; }
        const float inv = 1.f / s;
#pragma unroll
        for (int j = 0; j < D_HID; j++) p[j] = v[j] * inv;
    }
    __syncthreads();

    // ---- coalesced contiguous store (flattened)
    float* obase = out + (size_t)bid * (BM * TRANS_COLS);
    for (int idx = tid; idx < BM * TRANS_COLS; idx += NTHR) {
        const int r = idx / TRANS_COLS;
        const int c = idx - r * TRANS_COLS;
        obase[idx] = stag[r * STAG_PITCH + c];
    }
}

// ---------------------------------------------------------------------------
// launch
// ---------------------------------------------------------------------------
extern "C" void kernel_launch(void* const* d_in, const int* in_sizes, int n_in,
                              void* d_out, int out_size)
{
    const float* embs    = (const float*)d_in[0];
    const float* W_trans = (const float*)d_in[1];
    const float* b_trans = (const float*)d_in[2];
    const float* W_2o    = (const float*)d_in[3];
    const float* b_2o    = (const float*)d_in[4];
    const float* W_2e    = (const float*)d_in[5];
    const float* b_2e    = (const float*)d_in[6];
    const float* W_exp   = (const float*)d_in[7];
    const float* b_exp   = (const float*)d_in[8];
    const float* lut     = (const float*)d_in[9];
    float* out = (float*)d_out;

    cudaFuncSetAttribute(fused_kernel,
                         cudaFuncAttributeMaxDynamicSharedMemorySize, SM_TOTAL);

    // convert W to fp16 (320x768, zero-padded)
    convert_W_kernel<<<(N_PAD * D_EMB) / 256, 256>>>(W_trans);

    // fused: GEMM tiles (2 CTAs/SM) + tail small-path blocks
    fused_kernel<<<GRID_TOTAL, NTHR, SM_TOTAL>>>(
        embs, b_trans, W_2o, b_2o, W_2e, b_2e, W_exp, b_exp, lut, out);
}

// round 17
// speedup vs baseline: 1.3252x; 1.3252x over previous
#include <cuda_runtime.h>
#include <cuda_fp16.h>
#include <math.h>
#include <stdint.h>

// ---------------------------------------------------------------------------
// Problem constants
// ---------------------------------------------------------------------------
#define B_SZ    64
#define L_SZ    512
#define D_EMB   768
#define D_HID   17
#define D_OBS   17
#define N_SRC   24
#define NM1     16
#define TRANS_COLS (D_HID * D_HID)   // 289
#define M_ROWS  (B_SZ * L_SZ)        // 32768
#define N_PAD   320                  // padded B rows (289..319 zero)

// output layout (flattened concat of the 5 reference outputs, in order)
#define OFF_TRANS 0ULL
#define SZ_TRANS  ((size_t)M_ROWS * TRANS_COLS)
#define OFF_EMISS (OFF_TRANS + SZ_TRANS)
#define SZ_EMISS  ((size_t)B_SZ * N_SRC * TRANS_COLS)
#define OFF_O2O   (OFF_EMISS + SZ_EMISS)
#define SZ_O2O    ((size_t)B_SZ * N_SRC)
#define OFF_L2L   (OFF_O2O + SZ_O2O)
#define SZ_L2L    ((size_t)B_SZ * N_SRC * NM1)
#define OFF_WXOR  (OFF_L2L + SZ_L2L)
#define SZ_WXOR   ((size_t)B_SZ * N_SRC * NM1 * NM1)

// scratch (device globals; no allocations allowed)
__device__ __align__(16) __half g_Wh[N_PAD * D_EMB];

// ---------------------------------------------------------------------------
// Helpers (plain sm_100-compatible: mma.sync / ldmatrix / cp.async only)
// ---------------------------------------------------------------------------
__device__ __forceinline__ uint32_t smem_to_u32(const void* p) {
    uint32_t a;
    asm("{ .reg .u64 t; cvta.to.shared.u64 t, %1; cvt.u32.u64 %0, t; }" : "=r"(a) : "l"(p));
    return a;
}
__device__ __forceinline__ void mma16816(float* d, const uint32_t* a, uint32_t b0, uint32_t b1) {
    asm volatile("mma.sync.aligned.m16n8k16.row.col.f32.f16.f16.f32 "
        "{%0,%1,%2,%3},{%4,%5,%6,%7},{%8,%9},{%0,%1,%2,%3};"
        : "+f"(d[0]), "+f"(d[1]), "+f"(d[2]), "+f"(d[3])
        : "r"(a[0]), "r"(a[1]), "r"(a[2]), "r"(a[3]), "r"(b0), "r"(b1));
}
__device__ __forceinline__ void ldsm4(uint32_t* r, uint32_t addr) {
    asm volatile("ldmatrix.sync.aligned.m8n8.x4.shared.b16 {%0,%1,%2,%3}, [%4];"
        : "=r"(r[0]), "=r"(r[1]), "=r"(r[2]), "=r"(r[3]) : "r"(addr));
}
#define CP_ASYNC16(dst, src) \
    asm volatile("cp.async.cg.shared.global [%0], [%1], 16;" :: "r"(dst), "l"(src) : "memory")
#define CP_COMMIT() asm volatile("cp.async.commit_group;" ::: "memory")
#define CP_WAIT(n)  asm volatile("cp.async.wait_group %0;" :: "n"(n) : "memory")

// pack two fp32 -> half2 word (round-to-nearest)
__device__ __forceinline__ uint32_t pack2h(float x, float y) {
    __half hx = __float2half_rn(x), hy = __float2half_rn(y);
    return ((uint32_t)__half_as_ushort(hy) << 16) | __half_as_ushort(hx);
}
__device__ __forceinline__ float sigmoidf_(float x) { return 1.f / (1.f + __expf(-x)); }

// ---------------------------------------------------------------------------
// Kernel 0: convert W_trans to fp16, zero-pad rows 289..319
// ---------------------------------------------------------------------------
__global__ __launch_bounds__(256) void convert_W_kernel(const float* __restrict__ W)
{
    int idx = blockIdx.x * 256 + threadIdx.x;          // < 320*768
    int row = idx / D_EMB;
    float v = (row < TRANS_COLS) ? W[idx] : 0.f;
    g_Wh[idx] = __float2half_rn(v);
}

// ---------------------------------------------------------------------------
// Fused kernel: blocks 0..255 = GEMM tiles (128 rows x 320 cols, 4Mx4N warp
// tiling, plain fp16 MMA, 3-stage cp.async pipeline, one barrier/iter,
// fused bias+softmax); blocks 256..319 = per-batch small path.
// ---------------------------------------------------------------------------
#define BK        32
#define NK_ITERS  (D_EMB / BK)            // 24
#define PITCH     80                      // bytes per 32-fp16 row
#define NSTAGE    3
#define A_BUF_SZ  (128 * PITCH)           // 10240
#define B_BUF_SZ  (N_PAD * PITCH)         // 25600
#define SM_A      0                       // 3 stages x 10240 = 30720
#define SM_B      30720                   // 3 stages x 25600 = 76800 -> 107520
#define STAG_PITCH 305                    // staging 128x305x4 = 156160
#define SM_BIAS   156160                  // 289 floats
#define SM_TOTAL  157376

#define A_OFF(st)  (SM_A + (st) * A_BUF_SZ)
#define B_OFF(st)  (SM_B + (st) * B_BUF_SZ)

#define N_GEMM_BLOCKS 256
#define GRID_TOTAL    (N_GEMM_BLOCKS + B_SZ)

__global__ __launch_bounds__(512, 1) void fused_kernel(
    const float* __restrict__ embs,
    const float* __restrict__ bias,
    const float* __restrict__ W2o, const float* __restrict__ b2o,
    const float* __restrict__ W2e, const float* __restrict__ b2e,
    const float* __restrict__ Wexp, const float* __restrict__ bexp,
    const float* __restrict__ lut,
    float* __restrict__ out)
{
    extern __shared__ char smem[];
    const int bid = blockIdx.x;
    const int tid = threadIdx.x;

    if (bid >= N_GEMM_BLOCKS) {
        // =============== SMALL PATH: one block per batch row b ==============
        const int b = bid - N_GEMM_BLOCKS;
        float* x0   = (float*)smem;              // 768
        float* so2o = x0 + D_EMB;                // 24
        float* l2l  = so2o + N_SRC;              // 384
        float* wsc  = l2l + N_SRC * NM1;         // 384
        const int wid = tid >> 5, lane = tid & 31;

        const float* xrow = embs + (size_t)b * L_SZ * D_EMB;
        for (int i = tid; i < D_EMB; i += 512) x0[i] = xrow[i];
        __syncthreads();

        // 792 dot products, warp per column
        for (int col = wid; col < 24 + 2 * N_SRC * NM1; col += 16) {
            const float* w; float bv; float* dst; int isExp = 0;
            if (col < 24) {
                w = W2o + (size_t)col * D_EMB;  bv = b2o[col];  dst = &so2o[col];
            } else if (col < 24 + N_SRC * NM1) {
                int c = col - 24;
                w = W2e + (size_t)c * D_EMB;    bv = b2e[c];    dst = &l2l[c];
            } else {
                int c = col - 24 - N_SRC * NM1;
                w = Wexp + (size_t)c * D_EMB;   bv = bexp[c];   dst = &wsc[c]; isExp = 1;
            }
            float s = 0.f;
            for (int k = lane; k < D_EMB; k += 32) s = fmaf(x0[k], w[k], s);
#pragma unroll
            for (int o = 16; o > 0; o >>= 1) s += __shfl_xor_sync(0xffffffffu, s, o);
            if (lane == 0) {
                s += bv;
                *dst = isExp ? sigmoidf_(s) : s;
            }
        }
        __syncthreads();
        if (tid < N_SRC) so2o[tid] = sigmoidf_(so2o[tid]);
        __syncthreads();

        // softmax over 24 sources per column j + prob_scaling (warp j -> col j)
        if (wid < NM1) {
            const int j = wid;
            float x = (lane < N_SRC) ? l2l[lane * NM1 + j] : -1e30f;
            float mx = x;
#pragma unroll
            for (int o = 16; o > 0; o >>= 1) mx = fmaxf(mx, __shfl_xor_sync(0xffffffffu, mx, o));
            float e = (lane < N_SRC) ? __expf(x - mx) : 0.f;
            float s = e;
#pragma unroll
            for (int o = 16; o > 0; o >>= 1) s += __shfl_xor_sync(0xffffffffu, s, o);
            if (lane < N_SRC) {
                const float xn = e / s;
                const float r = 1.f / 24.f;
                const float omr = 1.f - r;
                const float bco = 1.f / (omr * omr * omr);
                float om = 1.f - xn;
                float om2 = om * om;
                l2l[lane * NM1 + j] = (xn < r) ? xn : (1.f - bco * om2 * om2);
            }
        }
        __syncthreads();

        if (tid < N_SRC) out[OFF_O2O + (size_t)b * N_SRC + tid] = so2o[tid];
        if (tid < N_SRC * NM1)
            out[OFF_L2L + (size_t)b * N_SRC * NM1 + tid] = l2l[tid];

        // scaled_wxor[b,s,i,j] = wsc[s,j] * lut[s,j,i]
        if (tid < N_SRC * NM1) {
            const int s = tid >> 4;
            const int i = tid & 15;
            float* dst = out + OFF_WXOR + (size_t)b * (N_SRC * NM1 * NM1) + (size_t)tid * NM1;
#pragma unroll
            for (int j = 0; j < NM1; j++)
                dst[j] = wsc[s * NM1 + j] * lut[s * 256 + j * NM1 + i];
        }

        // emission probs: 24 sources x 17 rows
        const float tp = 1.f / (float)D_OBS;
        if (tid < N_SRC * D_HID) {
            const int s   = tid / D_HID;
            const int row = tid - s * D_HID;
            float vals[D_HID];
            if (row == 0) {
                const float o = so2o[s];
                vals[0] = o;
                const float rest = (1.f - o) * (1.f / (float)NM1);
#pragma unroll
                for (int j = 1; j < D_HID; j++) vals[j] = rest;
            } else {
                const int i = row - 1;
                const float x = l2l[s * NM1 + i];
                const float wf = (x < tp) ? ((float)D_OBS * x * x) : x;
                const float omx = 1.f - x;
                vals[0] = omx * (1.f - wf);
                const float nd = omx * wf * (1.f / 15.f);
#pragma unroll
                for (int j = 0; j < NM1; j++) {
                    float base = (i == j) ? x : nd;
                    vals[j + 1] = base + wsc[s * NM1 + j] * lut[s * 256 + j * NM1 + i];
                }
            }
            float ssum = 0.f;
#pragma unroll
            for (int t = 0; t < D_HID; t++) {
                float rv = fmaf(vals[t], 99.f, 1.f);
                vals[t] = rv;
                ssum += rv;
            }
            const float inv = 1.f / ssum;
            float* dst = out + OFF_EMISS + (size_t)b * N_SRC * TRANS_COLS
                             + (size_t)s * TRANS_COLS + (size_t)row * D_HID;
#pragma unroll
            for (int t = 0; t < D_HID; t++) dst[t] = vals[t] * inv;
        }
        return;
    }

    // ====================== GEMM PATH ======================================
    const uint32_t smem_u = smem_to_u32(smem);
    const int wid  = tid >> 5;
    const int lane = tid & 31;
    const int mw   = wid >> 2;           // 0..3  (M warp: 32 rows, 2 m16 frags)
    const int nw   = wid & 3;            // 0..3  (N warp: 80 cols, 10 n8 tiles)
    const int m0   = bid * 128;

    // bias to smem
    for (int i = tid; i < TRANS_COLS; i += 512)
        *(float*)(smem + SM_BIAS + i * 4) = bias[i];

    // per-lane ldmatrix offsets
    const uint32_t aLaneOff = (uint32_t)((mw * 32 + (lane & 15)) * PITCH + (lane >> 4) * 16);
    const uint32_t rowInPair = (lane & 7) + ((lane & 16) >> 1);       // 0..15
    const uint32_t khalf = (lane >> 3) & 1;
    const uint32_t bLaneOff = (uint32_t)((nw * 80 + rowInPair) * PITCH + khalf * 16);

    // A global-load mapping: each thread loads 8 fp32 (2 float4) per chunk
    const int arow = tid >> 2;           // 0..127
    const int aq   = tid & 3;
    const float* aSrcBase = embs + (size_t)(m0 + arow) * D_EMB + aq * 8;

    float acc[20][4];                    // [m*10 + j][quad]
#pragma unroll
    for (int j = 0; j < 20; j++)
#pragma unroll
        for (int q = 0; q < 4; q++) acc[j][q] = 0.f;

    // ---- prologue: A regs chunk 0, B chunk 0 -> stage 0
    float4 aU = ((const float4*)(aSrcBase))[0];
    float4 aV = ((const float4*)(aSrcBase))[1];
    for (int c = tid; c < 1280; c += 512) {     // 320 rows x 4 segs
        const int r = c >> 2;
        const int seg = c & 3;
        const __half* src = g_Wh + (size_t)r * D_EMB + seg * 8;
        CP_ASYNC16(smem_u + B_OFF(0) + r * PITCH + seg * 16, src);
    }
    CP_COMMIT();

    for (int it = 0; it < NK_ITERS; it++) {
        const int st = it % NSTAGE;
        // prefetch B chunk it+1 into stage (it+1)%3.  Safe without trailing
        // barrier: the slowest warp is at most in compute of it-1, reading
        // stage (it-1)%3, which differs from (it+1)%3.
        if (it < NK_ITERS - 1) {
            const int k0 = (it + 1) * BK;
            const int stn = (it + 1) % NSTAGE;
            for (int c = tid; c < 1280; c += 512) {
                const int r = c >> 2;
                const int seg = c & 3;
                const __half* src = g_Wh + (size_t)r * D_EMB + k0 + seg * 8;
                CP_ASYNC16(smem_u + B_OFF(stn) + r * PITCH + seg * 16, src);
            }
            CP_COMMIT();
        }
        // convert A chunk it -> stage st (laggards read stage (it-1)%3)
        {
            uint32_t h0 = pack2h(aU.x, aU.y);
            uint32_t h1 = pack2h(aU.z, aU.w);
            uint32_t h2 = pack2h(aV.x, aV.y);
            uint32_t h3 = pack2h(aV.z, aV.w);
            const uint32_t d = arow * PITCH + aq * 16;
            *(uint4*)(smem + A_OFF(st) + d) = make_uint4(h0, h1, h2, h3);
        }
        if (it < NK_ITERS - 1) {
            const float* s = aSrcBase + (it + 1) * BK;
            aU = ((const float4*)s)[0];
            aV = ((const float4*)s)[1];
        }
        if (it < NK_ITERS - 1) { CP_WAIT(1); } else { CP_WAIT(0); }
        __syncthreads();   // single barrier per iteration

        // ---- compute on stage st (single fp16 term)
        const uint32_t aHi = smem_u + A_OFF(st) + aLaneOff;
        const uint32_t bHi = smem_u + B_OFF(st) + bLaneOff;
#pragma unroll
        for (int s = 0; s < 2; s++) {
            const uint32_t so = s * 32;
            uint32_t ah0[4], ah1[4];
            ldsm4(ah0, aHi + so);
            ldsm4(ah1, aHi + 16 * PITCH + so);
#pragma unroll
            for (int jp = 0; jp < 5; jp++) {
                const uint32_t off = jp * (16 * PITCH);
                uint32_t bh[4];
                ldsm4(bh, bHi + off + so);
                mma16816(acc[2*jp],      ah0, bh[0], bh[1]);
                mma16816(acc[2*jp+1],    ah0, bh[2], bh[3]);
                mma16816(acc[10+2*jp],   ah1, bh[0], bh[1]);
                mma16816(acc[10+2*jp+1], ah1, bh[2], bh[3]);
            }
        }
        // no trailing barrier (3-stage rotation guarantees safety)
    }
    __syncthreads();   // all compute done before smem is repurposed

    // ---- epilogue: accumulators -> staging smem
    float* stag = (float*)smem;
    {
        const int r0 = mw * 32 + (lane >> 2);
        const int nbase = nw * 80 + (lane & 3) * 2;
#pragma unroll
        for (int m = 0; m < 2; m++) {
            const int rA = r0 + m * 16;
#pragma unroll
            for (int j = 0; j < 10; j++) {
                const int n = nbase + j * 8;
                const float* a = acc[m * 10 + j];
                if (n < 288) {
                    stag[rA * STAG_PITCH + n]           = a[0];
                    stag[rA * STAG_PITCH + n + 1]       = a[1];
                    stag[(rA + 8) * STAG_PITCH + n]     = a[2];
                    stag[(rA + 8) * STAG_PITCH + n + 1] = a[3];
                } else if (n == 288) {
                    stag[rA * STAG_PITCH + 288]       = a[0];
                    stag[(rA + 8) * STAG_PITCH + 288] = a[2];
                }
            }
        }
    }
    __syncthreads();

    // ---- bias + softmax over contiguous 17-groups
    const float* biasS = (const float*)(smem + SM_BIAS);
    for (int t = tid; t < 128 * D_HID; t += 512) {
        const int row = t / D_HID;
        const int g = t - row * D_HID;
        float* p = stag + row * STAG_PITCH + g * D_HID;
        const float* bb = biasS + g * D_HID;
        float v[D_HID];
        float mx = -1e30f;
#pragma unroll
        for (int j = 0; j < D_HID; j++) { v[j] = p[j] + bb[j]; mx = fmaxf(mx, v[j]); }
        float s = 0.f;
#pragma unroll
        for (int j = 0; j < D_HID; j++) { float e = __expf(v[j] - mx); v[j] = e; s += e; }
        const float inv = 1.f / s;
#pragma unroll
        for (int j = 0; j < D_HID; j++) p[j] = v[j] * inv;
    }
    __syncthreads();

    // ---- coalesced contiguous store (flattened)
    float* obase = out + (size_t)bid * (128 * TRANS_COLS);
    for (int idx = tid; idx < 128 * TRANS_COLS; idx += 512) {
        const int r = idx / TRANS_COLS;
        const int c = idx - r * TRANS_COLS;
        obase[idx] = stag[r * STAG_PITCH + c];
    }
}

// ---------------------------------------------------------------------------
// launch
// ---------------------------------------------------------------------------
extern "C" void kernel_launch(void* const* d_in, const int* in_sizes, int n_in,
                              void* d_out, int out_size)
{
    const float* embs    = (const float*)d_in[0];
    const float* W_trans = (const float*)d_in[1];
    const float* b_trans = (const float*)d_in[2];
    const float* W_2o    = (const float*)d_in[3];
    const float* b_2o    = (const float*)d_in[4];
    const float* W_2e    = (const float*)d_in[5];
    const float* b_2e    = (const float*)d_in[6];
    const float* W_exp   = (const float*)d_in[7];
    const float* b_exp   = (const float*)d_in[8];
    const float* lut     = (const float*)d_in[9];
    float* out = (float*)d_out;

    cudaFuncSetAttribute(fused_kernel,
                         cudaFuncAttributeMaxDynamicSharedMemorySize, SM_TOTAL);

    // convert W to fp16 (320x768, zero-padded)
    convert_W_kernel<<<(N_PAD * D_EMB) / 256, 256>>>(W_trans);

    // fused: GEMM tiles + tail small-path blocks
    fused_kernel<<<GRID_TOTAL, 512, SM_TOTAL>>>(
        embs, b_trans, W_2o, b_2o, W_2e, b_2e, W_exp, b_exp, lut, out);
}